// round 1
// baseline (speedup 1.0000x reference)
#include <cuda_runtime.h>
#include <math.h>

#define BB 256
#define TT 512
#define DD 256
#define HH 64
#define KTAG 32
#define GH 192      // 3*H
#define NCOMB 384   // fw 192 | bw 192

// Scratch (allocation-free rule: __device__ globals)
__device__ float g_xp[(size_t)BB * TT * NCOMB];      // [b,t, fw(z,r,h)|bw(z,r,h)]
__device__ float g_hidden[(size_t)BB * TT * 2 * HH]; // [b,t, fw64|bw64]

// ---------------------------------------------------------------------------
// K1: Xp = X @ [fwK | bwK] + bias0   (M=131072, N=384, K=256)  classic SGEMM
// ---------------------------------------------------------------------------
__global__ __launch_bounds__(256) void proj_gemm(
    const float* __restrict__ X,
    const float* __restrict__ fwK, const float* __restrict__ bwK,
    const float* __restrict__ fwB, const float* __restrict__ bwB)
{
    const int BM = 128, BN = 128, BK = 8;
    __shared__ float As[BK][BM];
    __shared__ float Bs[BK][BN];

    int tid = threadIdx.x;
    int mTile = blockIdx.y, nTile = blockIdx.x;
    int tx = tid & 15, ty = tid >> 4;

    float acc[8][8];
#pragma unroll
    for (int i = 0; i < 8; i++)
#pragma unroll
        for (int j = 0; j < 8; j++) acc[i][j] = 0.f;

    int arow = tid >> 1;          // 0..127
    int acol = (tid & 1) * 4;     // 0 or 4
    int brow = tid >> 5;          // 0..7
    int bcol = (tid & 31) * 4;    // 0..124

    const float* Abase = X + (size_t)(mTile * BM) * DD;

    for (int k0 = 0; k0 < DD; k0 += BK) {
        float4 av = *(const float4*)(Abase + (size_t)arow * DD + k0 + acol);
        As[acol + 0][arow] = av.x;
        As[acol + 1][arow] = av.y;
        As[acol + 2][arow] = av.z;
        As[acol + 3][arow] = av.w;

        int n = nTile * BN + bcol;
        int k = k0 + brow;
        float4 bv;
        if (n < GH) bv = *(const float4*)(fwK + (size_t)k * GH + n);
        else        bv = *(const float4*)(bwK + (size_t)k * GH + (n - GH));
        *(float4*)(&Bs[brow][bcol]) = bv;

        __syncthreads();

#pragma unroll
        for (int kk = 0; kk < BK; kk++) {
            float a[8], b[8];
            *(float4*)(a)     = *(const float4*)(&As[kk][ty * 8]);
            *(float4*)(a + 4) = *(const float4*)(&As[kk][ty * 8 + 4]);
            *(float4*)(b)     = *(const float4*)(&Bs[kk][tx * 8]);
            *(float4*)(b + 4) = *(const float4*)(&Bs[kk][tx * 8 + 4]);
#pragma unroll
            for (int i = 0; i < 8; i++)
#pragma unroll
                for (int j = 0; j < 8; j++)
                    acc[i][j] = fmaf(a[i], b[j], acc[i][j]);
        }
        __syncthreads();
    }

    // epilogue: + input bias (bias row 0)
    float bias[8];
#pragma unroll
    for (int j = 0; j < 8; j++) {
        int n = nTile * BN + tx * 8 + j;
        bias[j] = (n < GH) ? fwB[n] : bwB[n - GH];
    }
#pragma unroll
    for (int i = 0; i < 8; i++) {
        size_t m = (size_t)mTile * BM + ty * 8 + i;
        float* o = g_xp + m * NCOMB + nTile * BN + tx * 8;
        float4 v0 = make_float4(acc[i][0] + bias[0], acc[i][1] + bias[1],
                                acc[i][2] + bias[2], acc[i][3] + bias[3]);
        float4 v1 = make_float4(acc[i][4] + bias[4], acc[i][5] + bias[5],
                                acc[i][6] + bias[6], acc[i][7] + bias[7]);
        *(float4*)(o)     = v0;
        *(float4*)(o + 4) = v1;
    }
}

// ---------------------------------------------------------------------------
// K2: bidirectional GRU recurrence. 1 block per batch; threads 0..191 = fw,
// 192..383 = bw. Recurrent weights in registers, h broadcast via smem.
// ---------------------------------------------------------------------------
__global__ __launch_bounds__(384) void gru_kernel(
    const float* __restrict__ rec_fw, const float* __restrict__ rec_bw,
    const float* __restrict__ bias_fw, const float* __restrict__ bias_bw,
    const int* __restrict__ mask)
{
    __shared__ float h_sm[2][HH];
    __shared__ float hp_sm[2][GH];

    int b = blockIdx.x;
    int tid = threadIdx.x;
    int dir = tid / GH;
    int j = tid - dir * GH;

    const float* rec = dir ? rec_bw : rec_fw;
    float rreg[HH];
#pragma unroll
    for (int i = 0; i < HH; i++) rreg[i] = rec[i * GH + j];
    float brj = (dir ? bias_bw : bias_fw)[GH + j];   // recurrent bias (row 1)

    if (j < HH) h_sm[dir][j] = 0.f;
    __syncthreads();

    const int gate = (j < HH);
    float pxz = 0.f, pxr = 0.f, pxh = 0.f;
    int pm = 1;
    if (gate) {
        int tt = dir ? (TT - 1) : 0;
        const float* xr0 = g_xp + ((size_t)b * TT + tt) * NCOMB + dir * GH;
        pxz = xr0[j]; pxr = xr0[HH + j]; pxh = xr0[2 * HH + j];
        pm = mask[b * TT + tt];
    }

    for (int t = 0; t < TT; t++) {
        float acc0 = brj, acc1 = 0.f;
        const float4* h4 = (const float4*)h_sm[dir];
#pragma unroll
        for (int i = 0; i < 16; i += 2) {
            float4 ha = h4[i];
            float4 hb = h4[i + 1];
            acc0 = fmaf(rreg[4 * i + 0], ha.x, acc0);
            acc0 = fmaf(rreg[4 * i + 1], ha.y, acc0);
            acc0 = fmaf(rreg[4 * i + 2], ha.z, acc0);
            acc0 = fmaf(rreg[4 * i + 3], ha.w, acc0);
            acc1 = fmaf(rreg[4 * i + 4], hb.x, acc1);
            acc1 = fmaf(rreg[4 * i + 5], hb.y, acc1);
            acc1 = fmaf(rreg[4 * i + 6], hb.z, acc1);
            acc1 = fmaf(rreg[4 * i + 7], hb.w, acc1);
        }
        hp_sm[dir][j] = acc0 + acc1;
        __syncthreads();

        if (gate) {
            int tt = dir ? (TT - 1 - t) : t;
            float hz = hp_sm[dir][j];
            float hr = hp_sm[dir][HH + j];
            float hc = hp_sm[dir][2 * HH + j];
            float hprev = h_sm[dir][j];
            float z = 1.f / (1.f + expf(-(pxz + hz)));
            float r = 1.f / (1.f + expf(-(pxr + hr)));
            float c = tanhf(pxh + r * hc);
            float hn = z * hprev + (1.f - z) * c;
            if (pm <= 0) hn = hprev;
            h_sm[dir][j] = hn;
            g_hidden[((size_t)b * TT + tt) * (2 * HH) + dir * HH + j] = hn;
            if (t + 1 < TT) {
                int tn = dir ? (TT - 2 - t) : (t + 1);
                const float* xr = g_xp + ((size_t)b * TT + tn) * NCOMB + dir * GH;
                pxz = xr[j]; pxr = xr[HH + j]; pxh = xr[2 * HH + j];
                pm = mask[b * TT + tn];
            }
        }
        __syncthreads();
    }
}

// ---------------------------------------------------------------------------
// K3: potentials = hidden @ dense + bias (+ boundaries at t=0 / t=T-1)
// warp per row, dense in smem
// ---------------------------------------------------------------------------
__global__ __launch_bounds__(256) void pot_kernel(
    const float* __restrict__ dk, const float* __restrict__ db,
    const float* __restrict__ lb, const float* __restrict__ rb,
    float* __restrict__ pot)
{
    __shared__ float ds[2 * HH * KTAG];   // [128][32]
    __shared__ float rows[8][2 * HH];

    int tid = threadIdx.x;
    for (int i = tid; i < 2 * HH * KTAG; i += 256) ds[i] = dk[i];

    int w = tid >> 5, lane = tid & 31;
    size_t row0 = (size_t)blockIdx.x * 8;

    {   // 8 rows * 128 floats = 256 float4, one per thread
        int r = tid >> 5;
        int c4 = (tid & 31) * 4;
        *(float4*)&rows[r][c4] =
            *(const float4*)(g_hidden + (row0 + r) * (2 * HH) + c4);
    }
    __syncthreads();

    float acc = db[lane];
#pragma unroll
    for (int h4 = 0; h4 < 32; h4++) {
        float4 hv = *(const float4*)&rows[w][h4 * 4];
        acc = fmaf(hv.x, ds[(4 * h4 + 0) * KTAG + lane], acc);
        acc = fmaf(hv.y, ds[(4 * h4 + 1) * KTAG + lane], acc);
        acc = fmaf(hv.z, ds[(4 * h4 + 2) * KTAG + lane], acc);
        acc = fmaf(hv.w, ds[(4 * h4 + 3) * KTAG + lane], acc);
    }
    size_t row = row0 + w;
    int t = (int)(row % TT);
    if (t == 0)      acc += lb[lane];
    if (t == TT - 1) acc += rb[lane];
    pot[row * KTAG + lane] = acc;
}

// ---------------------------------------------------------------------------
// K4: Viterbi (forward + backtrace in smem) + seq_len. Block per batch.
// thread k owns tag k; trans column k in registers.
// ---------------------------------------------------------------------------
__global__ __launch_bounds__(32) void viterbi_kernel(
    const float* __restrict__ pot, const float* __restrict__ trans,
    const int* __restrict__ mask,
    float* __restrict__ out_dec, float* __restrict__ out_len)
{
    __shared__ unsigned char bp[TT][KTAG];   // 16 KB
    __shared__ float ssm[KTAG];
    __shared__ unsigned char dec[TT];

    int b = blockIdx.x, k = threadIdx.x;

    float tr[KTAG];
#pragma unroll
    for (int j = 0; j < KTAG; j++) tr[j] = trans[j * KTAG + k];

    const float* pb = pot + (size_t)b * TT * KTAG;
    float s = pb[k];

    for (int t = 1; t < TT; t++) {
        ssm[k] = s;
        __syncwarp();
        float best = -INFINITY; int bj = 0;
#pragma unroll
        for (int j = 0; j < KTAG; j++) {
            float v = ssm[j] + tr[j];
            if (v > best) { best = v; bj = j; }
        }
        s = best + pb[(size_t)t * KTAG + k];
        bp[t][k] = (unsigned char)bj;
        __syncwarp();
    }

    ssm[k] = s;
    __syncwarp();
    if (k == 0) {
        float best = -INFINITY; int last = 0;
        for (int j = 0; j < KTAG; j++)
            if (ssm[j] > best) { best = ssm[j]; last = j; }
        int tag = last;
        dec[TT - 1] = (unsigned char)tag;
        for (int t = TT - 2; t >= 0; t--) {
            tag = bp[t + 1][tag];
            dec[t] = (unsigned char)tag;
        }
    }
    __syncwarp();

    for (int t = k; t < TT; t += 32)
        out_dec[(size_t)b * TT + t] = (float)dec[t];

    int sum = 0;
    for (int t = k; t < TT; t += 32) sum += mask[(size_t)b * TT + t];
#pragma unroll
    for (int o = 16; o > 0; o >>= 1) sum += __shfl_down_sync(0xffffffffu, sum, o);
    if (k == 0) out_len[b] = (float)sum;
}

// K5: copy chain_kernel into the output tail
__global__ void tail_kernel(const float* __restrict__ chain, float* __restrict__ outc)
{
    int i = threadIdx.x + blockIdx.x * blockDim.x;
    if (i < KTAG * KTAG) outc[i] = chain[i];
}

// ---------------------------------------------------------------------------
extern "C" void kernel_launch(void* const* d_in, const int* in_sizes, int n_in,
                              void* d_out, int out_size)
{
    const float* X      = (const float*)d_in[0];
    const int*   mask   = (const int*)d_in[1];
    const float* fwK    = (const float*)d_in[2];
    const float* fwR    = (const float*)d_in[3];
    const float* fwBias = (const float*)d_in[4];
    const float* bwK    = (const float*)d_in[5];
    const float* bwR    = (const float*)d_in[6];
    const float* bwBias = (const float*)d_in[7];
    const float* dK     = (const float*)d_in[8];
    const float* dB     = (const float*)d_in[9];
    const float* chain  = (const float*)d_in[10];
    const float* lb     = (const float*)d_in[11];
    const float* rb     = (const float*)d_in[12];

    float* out       = (float*)d_out;
    float* out_dec   = out;                              // B*T
    float* pot       = out + (size_t)BB * TT;            // B*T*K
    float* out_len   = pot + (size_t)BB * TT * KTAG;     // B
    float* out_chain = out_len + BB;                     // K*K

    dim3 g1(NCOMB / 128, (BB * TT) / 128);
    proj_gemm<<<g1, 256>>>(X, fwK, bwK, fwBias, bwBias);
    gru_kernel<<<BB, 384>>>(fwR, bwR, fwBias, bwBias, mask);
    pot_kernel<<<(BB * TT) / 8, 256>>>(dK, dB, lb, rb, pot);
    viterbi_kernel<<<BB, 32>>>(pot, chain, mask, out_dec, out_len);
    tail_kernel<<<4, 256>>>(chain, out_chain);
}

// round 2
// speedup vs baseline: 1.1502x; 1.1502x over previous
#include <cuda_runtime.h>
#include <math.h>

#define BB 256
#define TT 512
#define DD 256
#define HH 64
#define KTAG 32
#define GH 192      // 3*H
#define NCOMB 384   // fw 192 | bw 192

// Scratch (allocation-free rule: __device__ globals)
__device__ float g_xp[(size_t)BB * TT * NCOMB];      // [b,t, fw(z,r,h)|bw(z,r,h)]
__device__ float g_hidden[(size_t)BB * TT * 2 * HH]; // [b,t, fw64|bw64]

// packed fp32x2 helpers (Blackwell: 2x fp32 throughput, PTX-only)
#define FFMA2(acc, a, b) \
    asm("fma.rn.f32x2 %0, %1, %2, %0;" : "+l"(acc) : "l"(a), "l"(b))
#define PACK2(out, lo, hi) \
    asm("mov.b64 %0, {%1, %2};" : "=l"(out) : "r"(__float_as_uint(lo)), "r"(__float_as_uint(hi)))
#define UNPACK2(lo, hi, in) \
    asm("mov.b64 {%0, %1}, %2;" : "=f"(lo), "=f"(hi) : "l"(in))

// ---------------------------------------------------------------------------
// K1: Xp = X @ [fwK | bwK] + bias0   (M=131072, N=384, K=256)
// 128x128x8 tile, 8x8 per thread, f32x2-packed accumulation (8x4 packed).
// ---------------------------------------------------------------------------
__global__ __launch_bounds__(256) void proj_gemm(
    const float* __restrict__ X,
    const float* __restrict__ fwK, const float* __restrict__ bwK,
    const float* __restrict__ fwB, const float* __restrict__ bwB)
{
    const int BM = 128, BN = 128, BK = 8;
    __shared__ float As[BK][BM];
    __shared__ float Bs[BK][BN];

    int tid = threadIdx.x;
    int mTile = blockIdx.y, nTile = blockIdx.x;
    int tx = tid & 15, ty = tid >> 4;

    unsigned long long acc2[8][4];
#pragma unroll
    for (int i = 0; i < 8; i++)
#pragma unroll
        for (int j = 0; j < 4; j++) acc2[i][j] = 0ULL;  // (0.f, 0.f)

    int arow = tid >> 1;          // 0..127
    int acol = (tid & 1) * 4;     // 0 or 4
    int brow = tid >> 5;          // 0..7
    int bcol = (tid & 31) * 4;    // 0..124

    const float* Abase = X + (size_t)(mTile * BM) * DD;

    for (int k0 = 0; k0 < DD; k0 += BK) {
        float4 av = *(const float4*)(Abase + (size_t)arow * DD + k0 + acol);
        As[acol + 0][arow] = av.x;
        As[acol + 1][arow] = av.y;
        As[acol + 2][arow] = av.z;
        As[acol + 3][arow] = av.w;

        int n = nTile * BN + bcol;
        int k = k0 + brow;
        float4 bv;
        if (n < GH) bv = *(const float4*)(fwK + (size_t)k * GH + n);
        else        bv = *(const float4*)(bwK + (size_t)k * GH + (n - GH));
        *(float4*)(&Bs[brow][bcol]) = bv;

        __syncthreads();

#pragma unroll
        for (int kk = 0; kk < BK; kk++) {
            float a[8];
            *(float4*)(a)     = *(const float4*)(&As[kk][ty * 8]);
            *(float4*)(a + 4) = *(const float4*)(&As[kk][ty * 8 + 4]);
            const unsigned long long* b2 =
                (const unsigned long long*)(&Bs[kk][tx * 8]);
            unsigned long long bb[4];
            bb[0] = b2[0]; bb[1] = b2[1]; bb[2] = b2[2]; bb[3] = b2[3];
#pragma unroll
            for (int i = 0; i < 8; i++) {
                unsigned long long aa;
                PACK2(aa, a[i], a[i]);
#pragma unroll
                for (int j = 0; j < 4; j++)
                    FFMA2(acc2[i][j], aa, bb[j]);
            }
        }
        __syncthreads();
    }

    // epilogue: + input bias (bias row 0)
    float bias[8];
#pragma unroll
    for (int j = 0; j < 8; j++) {
        int n = nTile * BN + tx * 8 + j;
        bias[j] = (n < GH) ? fwB[n] : bwB[n - GH];
    }
#pragma unroll
    for (int i = 0; i < 8; i++) {
        size_t m = (size_t)mTile * BM + ty * 8 + i;
        float* o = g_xp + m * NCOMB + nTile * BN + tx * 8;
        float c[8];
#pragma unroll
        for (int j = 0; j < 4; j++) {
            float lo, hi;
            UNPACK2(lo, hi, acc2[i][j]);
            c[2 * j] = lo + bias[2 * j];
            c[2 * j + 1] = hi + bias[2 * j + 1];
        }
        *(float4*)(o)     = make_float4(c[0], c[1], c[2], c[3]);
        *(float4*)(o + 4) = make_float4(c[4], c[5], c[6], c[7]);
    }
}

// ---------------------------------------------------------------------------
// K2: GRU recurrence. grid=(B, 2dirs), block=192. Recurrent weights packed in
// registers (f32x2), h broadcast via smem.
// ---------------------------------------------------------------------------
__global__ __launch_bounds__(192) void gru_kernel(
    const float* __restrict__ rec_fw, const float* __restrict__ rec_bw,
    const float* __restrict__ bias_fw, const float* __restrict__ bias_bw,
    const int* __restrict__ mask)
{
    __shared__ float h_sm[HH];
    __shared__ float hp_sm[GH];

    int b = blockIdx.x;
    int dir = blockIdx.y;
    int j = threadIdx.x;

    const float* rec = dir ? rec_bw : rec_fw;
    unsigned long long rp[HH / 2];
#pragma unroll
    for (int i = 0; i < HH / 2; i++) {
        float r0 = rec[(2 * i) * GH + j];
        float r1 = rec[(2 * i + 1) * GH + j];
        PACK2(rp[i], r0, r1);
    }
    float brj = (dir ? bias_bw : bias_fw)[GH + j];   // recurrent bias (row 1)

    if (j < HH) h_sm[j] = 0.f;
    __syncthreads();

    const int gate = (j < HH);
    float pxz = 0.f, pxr = 0.f, pxh = 0.f;
    int pm = 1;
    if (gate) {
        int tt = dir ? (TT - 1) : 0;
        const float* xr0 = g_xp + ((size_t)b * TT + tt) * NCOMB + dir * GH;
        pxz = xr0[j]; pxr = xr0[HH + j]; pxh = xr0[2 * HH + j];
        pm = mask[b * TT + tt];
    }

    for (int t = 0; t < TT; t++) {
        unsigned long long accA = 0ULL, accB = 0ULL;
        const unsigned long long* h2 = (const unsigned long long*)h_sm;
#pragma unroll
        for (int i = 0; i < HH / 2; i += 2) {
            FFMA2(accA, rp[i], h2[i]);
            FFMA2(accB, rp[i + 1], h2[i + 1]);
        }
        float a0, a1, b0, b1;
        UNPACK2(a0, a1, accA);
        UNPACK2(b0, b1, accB);
        hp_sm[j] = (a0 + a1) + (b0 + b1) + brj;
        __syncthreads();

        if (gate) {
            int tt = dir ? (TT - 1 - t) : t;
            float hz = hp_sm[j];
            float hr = hp_sm[HH + j];
            float hc = hp_sm[2 * HH + j];
            float hprev = h_sm[j];
            float z = 1.f / (1.f + expf(-(pxz + hz)));
            float r = 1.f / (1.f + expf(-(pxr + hr)));
            float c = tanhf(pxh + r * hc);
            float hn = z * hprev + (1.f - z) * c;
            if (pm <= 0) hn = hprev;
            h_sm[j] = hn;
            g_hidden[((size_t)b * TT + tt) * (2 * HH) + dir * HH + j] = hn;
            if (t + 1 < TT) {
                int tn = dir ? (TT - 2 - t) : (t + 1);
                const float* xr = g_xp + ((size_t)b * TT + tn) * NCOMB + dir * GH;
                pxz = xr[j]; pxr = xr[HH + j]; pxh = xr[2 * HH + j];
                pm = mask[b * TT + tn];
            }
        }
        __syncthreads();
    }
}

// ---------------------------------------------------------------------------
// K3: potentials = hidden @ dense + bias (+ boundaries at t=0 / t=T-1)
// ---------------------------------------------------------------------------
__global__ __launch_bounds__(256) void pot_kernel(
    const float* __restrict__ dk, const float* __restrict__ db,
    const float* __restrict__ lb, const float* __restrict__ rb,
    float* __restrict__ pot)
{
    __shared__ float ds[2 * HH * KTAG];   // [128][32]
    __shared__ float rows[8][2 * HH];

    int tid = threadIdx.x;
    for (int i = tid; i < 2 * HH * KTAG; i += 256) ds[i] = dk[i];

    int w = tid >> 5, lane = tid & 31;
    size_t row0 = (size_t)blockIdx.x * 8;

    {
        int r = tid >> 5;
        int c4 = (tid & 31) * 4;
        *(float4*)&rows[r][c4] =
            *(const float4*)(g_hidden + (row0 + r) * (2 * HH) + c4);
    }
    __syncthreads();

    float acc = db[lane];
#pragma unroll
    for (int h4 = 0; h4 < 32; h4++) {
        float4 hv = *(const float4*)&rows[w][h4 * 4];
        acc = fmaf(hv.x, ds[(4 * h4 + 0) * KTAG + lane], acc);
        acc = fmaf(hv.y, ds[(4 * h4 + 1) * KTAG + lane], acc);
        acc = fmaf(hv.z, ds[(4 * h4 + 2) * KTAG + lane], acc);
        acc = fmaf(hv.w, ds[(4 * h4 + 3) * KTAG + lane], acc);
    }
    size_t row = row0 + w;
    int t = (int)(row % TT);
    if (t == 0)      acc += lb[lane];
    if (t == TT - 1) acc += rb[lane];
    pot[row * KTAG + lane] = acc;
}

// ---------------------------------------------------------------------------
// K4: Viterbi. Block per batch, 1 warp. s broadcast via shfl (no smem, no
// barrier), pot prefetched 8 steps ahead, argmax via 4 independent chains
// merged with index-aware ties (matches jnp.argmax first-max).
// ---------------------------------------------------------------------------
__device__ __forceinline__ void amerge(float& mv, int& mi, float v, int i)
{
    if (v > mv || (v == mv && i < mi)) { mv = v; mi = i; }
}

__global__ __launch_bounds__(32) void viterbi_kernel(
    const float* __restrict__ pot, const float* __restrict__ trans,
    const int* __restrict__ mask,
    float* __restrict__ out_dec, float* __restrict__ out_len)
{
    __shared__ unsigned char bp[TT][KTAG];   // 16 KB
    __shared__ unsigned char dec[TT];

    int b = blockIdx.x, k = threadIdx.x;

    float tr[KTAG];
#pragma unroll
    for (int j = 0; j < KTAG; j++) tr[j] = trans[j * KTAG + k];

    const float* pb = pot + (size_t)b * TT * KTAG;
    float s = pb[k];

    for (int t0 = 1; t0 < TT; t0 += 8) {
        float pv[8];
#pragma unroll
        for (int u = 0; u < 8; u++) {
            int t = t0 + u;
            pv[u] = (t < TT) ? pb[(size_t)t * KTAG + k] : 0.f;
        }
#pragma unroll
        for (int u = 0; u < 8; u++) {
            int t = t0 + u;
            if (t >= TT) break;
            float m0 = -INFINITY, m1 = -INFINITY, m2 = -INFINITY, m3 = -INFINITY;
            int i0 = 0, i1 = 1, i2 = 2, i3 = 3;
#pragma unroll
            for (int j = 0; j < KTAG; j += 4) {
                float v0 = __shfl_sync(0xffffffffu, s, j)     + tr[j];
                float v1 = __shfl_sync(0xffffffffu, s, j + 1) + tr[j + 1];
                float v2 = __shfl_sync(0xffffffffu, s, j + 2) + tr[j + 2];
                float v3 = __shfl_sync(0xffffffffu, s, j + 3) + tr[j + 3];
                if (v0 > m0) { m0 = v0; i0 = j; }
                if (v1 > m1) { m1 = v1; i1 = j + 1; }
                if (v2 > m2) { m2 = v2; i2 = j + 2; }
                if (v3 > m3) { m3 = v3; i3 = j + 3; }
            }
            amerge(m0, i0, m1, i1);
            amerge(m2, i2, m3, i3);
            amerge(m0, i0, m2, i2);
            s = m0 + pv[u];
            bp[t][k] = (unsigned char)i0;
        }
    }

    // argmax over final scores (all lanes compute; lane 0 uses it)
    float m0 = -INFINITY, m1 = -INFINITY, m2 = -INFINITY, m3 = -INFINITY;
    int i0 = 0, i1 = 1, i2 = 2, i3 = 3;
#pragma unroll
    for (int j = 0; j < KTAG; j += 4) {
        float v0 = __shfl_sync(0xffffffffu, s, j);
        float v1 = __shfl_sync(0xffffffffu, s, j + 1);
        float v2 = __shfl_sync(0xffffffffu, s, j + 2);
        float v3 = __shfl_sync(0xffffffffu, s, j + 3);
        if (v0 > m0) { m0 = v0; i0 = j; }
        if (v1 > m1) { m1 = v1; i1 = j + 1; }
        if (v2 > m2) { m2 = v2; i2 = j + 2; }
        if (v3 > m3) { m3 = v3; i3 = j + 3; }
    }
    amerge(m0, i0, m1, i1);
    amerge(m2, i2, m3, i3);
    amerge(m0, i0, m2, i2);

    __syncwarp();
    if (k == 0) {
        int tag = i0;
        dec[TT - 1] = (unsigned char)tag;
        for (int t = TT - 2; t >= 0; t--) {
            tag = bp[t + 1][tag];
            dec[t] = (unsigned char)tag;
        }
    }
    __syncwarp();

    for (int t = k; t < TT; t += 32)
        out_dec[(size_t)b * TT + t] = (float)dec[t];

    int sum = 0;
    for (int t = k; t < TT; t += 32) sum += mask[(size_t)b * TT + t];
#pragma unroll
    for (int o = 16; o > 0; o >>= 1) sum += __shfl_down_sync(0xffffffffu, sum, o);
    if (k == 0) out_len[b] = (float)sum;
}

// K5: copy chain_kernel into the output tail
__global__ void tail_kernel(const float* __restrict__ chain, float* __restrict__ outc)
{
    int i = threadIdx.x + blockIdx.x * blockDim.x;
    if (i < KTAG * KTAG) outc[i] = chain[i];
}

// ---------------------------------------------------------------------------
extern "C" void kernel_launch(void* const* d_in, const int* in_sizes, int n_in,
                              void* d_out, int out_size)
{
    const float* X      = (const float*)d_in[0];
    const int*   mask   = (const int*)d_in[1];
    const float* fwK    = (const float*)d_in[2];
    const float* fwR    = (const float*)d_in[3];
    const float* fwBias = (const float*)d_in[4];
    const float* bwK    = (const float*)d_in[5];
    const float* bwR    = (const float*)d_in[6];
    const float* bwBias = (const float*)d_in[7];
    const float* dK     = (const float*)d_in[8];
    const float* dB     = (const float*)d_in[9];
    const float* chain  = (const float*)d_in[10];
    const float* lb     = (const float*)d_in[11];
    const float* rb     = (const float*)d_in[12];

    float* out       = (float*)d_out;
    float* out_dec   = out;                              // B*T
    float* pot       = out + (size_t)BB * TT;            // B*T*K
    float* out_len   = pot + (size_t)BB * TT * KTAG;     // B
    float* out_chain = out_len + BB;                     // K*K

    dim3 g1(NCOMB / 128, (BB * TT) / 128);
    proj_gemm<<<g1, 256>>>(X, fwK, bwK, fwBias, bwBias);
    dim3 g2(BB, 2);
    gru_kernel<<<g2, GH>>>(fwR, bwR, fwBias, bwBias, mask);
    pot_kernel<<<(BB * TT) / 8, 256>>>(dK, dB, lb, rb, pot);
    viterbi_kernel<<<BB, 32>>>(pot, chain, mask, out_dec, out_len);
    tail_kernel<<<4, 256>>>(chain, out_chain);
}